// round 4
// baseline (speedup 1.0000x reference)
#include <cuda_runtime.h>
#include <math.h>

#define T_STEPS 8192
#define M_DIM   1024
#define N_DIM   2048

#define GBLOCKS        128
#define ROWS_PER_BLOCK 16    // N_DIM / GBLOCKS
#define RNN_THREADS    256

// Scratch for the batched input projection (allocation-free rule: device global).
__device__ float g_pre[(size_t)T_STEPS * N_DIM];

// Self-validating h packets: packet j = { f32 h[j] (low 32), u32 tag (high 32) }.
// 8B aligned loads/stores are single-copy atomic -> tag and value never tear,
// so NO fences or flags are needed: seeing tag==g implies h is valid.
// 4-deep ring indexed by tag&3. Tags advance by exactly T_STEPS per launch,
// uniformly across all packets, so the epoch base is recoverable at launch
// start from any packet's ring (graph-replay safe; signed compares handle wrap).
__device__ unsigned long long g_pk[4][N_DIM];

// ---------------------------------------------------------------------------
// Inline PTX helpers
// ---------------------------------------------------------------------------
__device__ __forceinline__ unsigned long long ldg_cv_u64(const unsigned long long* p) {
    unsigned long long v;
    asm volatile("ld.global.cv.u64 %0, [%1];" : "=l"(v) : "l"(p) : "memory");
    return v;
}
__device__ __forceinline__ void stg_u64(unsigned long long* p, unsigned long long v) {
    asm volatile("st.global.u64 [%0], %1;" :: "l"(p), "l"(v) : "memory");
}
__device__ __forceinline__ unsigned long long pack_pk(float h, unsigned tag) {
    return (unsigned long long)__float_as_uint(h) | ((unsigned long long)tag << 32);
}
__device__ __forceinline__ void fma2(unsigned long long& d,
                                     unsigned long long a,
                                     unsigned long long b) {
    asm("fma.rn.f32x2 %0, %1, %2, %3;" : "=l"(d) : "l"(a), "l"(b), "l"(d));
}
__device__ __forceinline__ unsigned long long add2(unsigned long long a,
                                                   unsigned long long b) {
    unsigned long long d;
    asm("add.rn.f32x2 %0, %1, %2;" : "=l"(d) : "l"(a), "l"(b));
    return d;
}
__device__ __forceinline__ float hsum2(unsigned long long v) {
    float lo, hi;
    asm("mov.b64 {%0, %1}, %2;" : "=f"(lo), "=f"(hi) : "l"(v));
    return lo + hi;
}

// ---------------------------------------------------------------------------
// Kernel 1: pre = X @ W_ih^T + (b_ih + b_hh)   (unchanged, proven)
// ---------------------------------------------------------------------------
__global__ __launch_bounds__(256) void gemm_pre_kernel(
    const float* __restrict__ X,
    const float* __restrict__ Wih,
    const float* __restrict__ b_ih,
    const float* __restrict__ b_hh)
{
    __shared__ float As[8][128];
    __shared__ float Bs[8][128];

    const int tid = threadIdx.x;
    const int rowBase = blockIdx.x * 128;
    const int colBase = blockIdx.y * 128;
    const int tx = tid & 15;
    const int ty = tid >> 4;

    float acc[8][8];
#pragma unroll
    for (int i = 0; i < 8; i++)
#pragma unroll
        for (int j = 0; j < 8; j++) acc[i][j] = 0.0f;

    const int lr = tid >> 1;
    const int lq = (tid & 1) * 4;

    for (int k0 = 0; k0 < M_DIM; k0 += 8) {
        float4 av = *(const float4*)&X  [(size_t)(rowBase + lr) * M_DIM + k0 + lq];
        float4 bv = *(const float4*)&Wih[(size_t)(colBase + lr) * M_DIM + k0 + lq];

        __syncthreads();
        As[lq + 0][lr] = av.x;
        As[lq + 1][lr] = av.y;
        As[lq + 2][lr] = av.z;
        As[lq + 3][lr] = av.w;
        Bs[lq + 0][lr] = bv.x;
        Bs[lq + 1][lr] = bv.y;
        Bs[lq + 2][lr] = bv.z;
        Bs[lq + 3][lr] = bv.w;
        __syncthreads();

#pragma unroll
        for (int k = 0; k < 8; k++) {
            float4 a0 = ((const float4*)As[k])[ty];
            float4 a1 = ((const float4*)As[k])[ty + 16];
            float4 b0 = ((const float4*)Bs[k])[tx];
            float4 b1 = ((const float4*)Bs[k])[tx + 16];
            float a[8] = {a0.x, a0.y, a0.z, a0.w, a1.x, a1.y, a1.z, a1.w};
            float b[8] = {b0.x, b0.y, b0.z, b0.w, b1.x, b1.y, b1.z, b1.w};
#pragma unroll
            for (int i = 0; i < 8; i++)
#pragma unroll
                for (int j = 0; j < 8; j++)
                    acc[i][j] = fmaf(a[i], b[j], acc[i][j]);
        }
    }

    const int n0 = colBase + tx * 4;
    const int n1 = colBase + 64 + tx * 4;
    float bias[8];
#pragma unroll
    for (int j = 0; j < 4; j++) {
        bias[j]     = b_ih[n0 + j] + b_hh[n0 + j];
        bias[j + 4] = b_ih[n1 + j] + b_hh[n1 + j];
    }

#pragma unroll
    for (int i = 0; i < 8; i++) {
        int m = rowBase + ((i < 4) ? (ty * 4 + i) : (64 + ty * 4 + (i - 4)));
        float4 o0, o1;
        o0.x = acc[i][0] + bias[0];
        o0.y = acc[i][1] + bias[1];
        o0.z = acc[i][2] + bias[2];
        o0.w = acc[i][3] + bias[3];
        o1.x = acc[i][4] + bias[4];
        o1.y = acc[i][5] + bias[5];
        o1.z = acc[i][6] + bias[6];
        o1.w = acc[i][7] + bias[7];
        *(float4*)&g_pre[(size_t)m * N_DIM + n0] = o0;
        *(float4*)&g_pre[(size_t)m * N_DIM + n1] = o1;
    }
}

// ---------------------------------------------------------------------------
// Kernel 2: persistent RNN recurrence with tagged-packet h exchange.
// Block b owns h rows [16b, 16b+16); warp w computes rows 16b+2w, +1 with
// W_hh register-resident. Step-t handshake: consumers poll the step-(t-1)
// packets directly (data+tag in one 8B word); each thread gathers 8 packets
// into SMEM (double-buffered), one __syncthreads, then the dot products read
// h from SMEM. Producers publish per-warp as soon as their reduce finishes.
// Tag ring invariant: a slot for tag g is overwritten only by tag g+4, which
// requires its producer to have consumed ALL tag g+2 packets -> every block
// finished reading tag g long before (skew across blocks is at most 1 step).
// ---------------------------------------------------------------------------
__global__ __launch_bounds__(RNN_THREADS, 1) void rnn_kernel(
    const float* __restrict__ Whh,
    float* __restrict__ Y)
{
    __shared__ float sh[2][N_DIM];   // double-buffered h staging (16 KB)

    const int tid  = threadIdx.x;
    const int b    = blockIdx.x;
    const int warp = tid >> 5;
    const int lane = tid & 31;
    const int row0 = b * ROWS_PER_BLOCK + 2 * warp;

    // Warp's two W_hh rows in registers, pre-packed as f32x2 pairs.
    unsigned long long wA[32], wB[32];
    {
        const ulonglong2* WA = (const ulonglong2*)(Whh + (size_t)row0 * N_DIM);
        const ulonglong2* WB = (const ulonglong2*)(Whh + (size_t)(row0 + 1) * N_DIM);
#pragma unroll
        for (int i = 0; i < 16; i++) {
            ulonglong2 va = WA[i * 32 + lane];
            ulonglong2 vb = WB[i * 32 + lane];
            wA[2 * i]     = va.x;
            wA[2 * i + 1] = va.y;
            wB[2 * i]     = vb.x;
            wB[2 * i + 1] = vb.y;
        }
    }

    // Epoch base: max tag in the ring of a packet OWNED BY THIS BLOCK
    // (packet index 16b, written only by this block's warp 0 — and not yet
    // this launch, because the barrier below precedes any publish).
    unsigned base = 0;
#pragma unroll
    for (int r = 0; r < 4; r++) {
        unsigned tg = (unsigned)(ldg_cv_u64(&g_pk[r][b * ROWS_PER_BLOCK]) >> 32);
        if ((int)(tg - base) > 0) base = tg;
    }
    __syncthreads();   // all threads have read base before any packet write

    // Step 0: h_0 = 0  =>  h = tanh(pre[0]); publish with tag base+1.
    if (lane == 0) {
        const float2 p0 = *(const float2*)(g_pre + row0);
        float h0 = tanhf(p0.x);
        float h1 = tanhf(p0.y);
        unsigned tag = base + 1u;
        stg_u64(&g_pk[tag & 3u][row0],     pack_pk(h0, tag));
        stg_u64(&g_pk[tag & 3u][row0 + 1], pack_pk(h1, tag));
        float2 o; o.x = h0; o.y = h1;
        *(float2*)(Y + row0) = o;
    }

    // Prefetch pre for step 1.
    float2 pv = *(const float2*)(g_pre + (size_t)N_DIM + row0);

    for (int t = 1; t < T_STEPS; t++) {
        const unsigned want = base + (unsigned)t;      // tag of step t-1
        const unsigned long long* src = &g_pk[want & 3u][tid * 8];

        // Poll my 8 packets (MLP=8 first pass, then re-load laggards).
        unsigned long long v[8];
#pragma unroll
        for (int k = 0; k < 8; k++) v[k] = ldg_cv_u64(src + k);
        for (;;) {
            bool all_ok = true;
#pragma unroll
            for (int k = 0; k < 8; k++) {
                if ((int)((unsigned)(v[k] >> 32) - want) < 0) {
                    all_ok = false;
                    v[k] = ldg_cv_u64(src + k);
                }
            }
            if (all_ok) break;
        }

        // Stage h into the step-parity SMEM buffer.
        float* dst = &sh[want & 1u][tid * 8];
#pragma unroll
        for (int k = 0; k < 8; k++) dst[k] = __uint_as_float((unsigned)v[k]);
        __syncthreads();

        // Dot products from SMEM (conflict-free 16B pattern).
        const ulonglong2* hp = (const ulonglong2*)sh[want & 1u];
        unsigned long long acc00 = 0ull, acc01 = 0ull, acc10 = 0ull, acc11 = 0ull;
#pragma unroll
        for (int i = 0; i < 16; i++) {
            ulonglong2 hv = hp[i * 32 + lane];
            fma2(acc00, wA[2 * i],     hv.x);
            fma2(acc01, wA[2 * i + 1], hv.y);
            fma2(acc10, wB[2 * i],     hv.x);
            fma2(acc11, wB[2 * i + 1], hv.y);
        }
        float r0 = hsum2(add2(acc00, acc01));
        float r1 = hsum2(add2(acc10, acc11));

#pragma unroll
        for (int o = 16; o; o >>= 1) {
            r0 += __shfl_xor_sync(0xffffffffu, r0, o);
            r1 += __shfl_xor_sync(0xffffffffu, r1, o);
        }

        // Prefetch next step's pre.
        float2 pnext = pv;
        if (t + 1 < T_STEPS)
            pnext = *(const float2*)(g_pre + (size_t)(t + 1) * N_DIM + row0);

        // Publish h_t per-warp, immediately (tag rides with the data).
        if (lane == 0) {
            float h0 = tanhf(pv.x + r0);
            float h1 = tanhf(pv.y + r1);
            const unsigned tag = want + 1u;
            stg_u64(&g_pk[tag & 3u][row0],     pack_pk(h0, tag));
            stg_u64(&g_pk[tag & 3u][row0 + 1], pack_pk(h1, tag));
            float2 o; o.x = h0; o.y = h1;
            *(float2*)(Y + (size_t)t * N_DIM + row0) = o;
        }
        pv = pnext;
    }
}

// ---------------------------------------------------------------------------
extern "C" void kernel_launch(void* const* d_in, const int* in_sizes, int n_in,
                              void* d_out, int out_size)
{
    const float* X   = (const float*)d_in[0];   // [T, M]
    const float* Wih = (const float*)d_in[1];   // [N, M]
    const float* Whh = (const float*)d_in[2];   // [N, N]
    const float* bih = (const float*)d_in[3];   // [N]
    const float* bhh = (const float*)d_in[4];   // [N]
    float* Y = (float*)d_out;                   // [T, N]

    dim3 ggrid(T_STEPS / 128, N_DIM / 128);
    gemm_pre_kernel<<<ggrid, 256>>>(X, Wih, bih, bhh);

    rnn_kernel<<<GBLOCKS, RNN_THREADS>>>(Whh, Y);
}